// round 1
// baseline (speedup 1.0000x reference)
#include <cuda_runtime.h>

// ---------------- problem constants ----------------
#define D_DIM  512
#define HID    513
#define P_CTX  8192
#define KTEST  2048
#define LDEPTH 8
#define HID2   (HID*HID)
#define NSPLIT 8
#define CHUNK  (P_CTX/NSPLIT)

// ---------------- scratch (no allocations allowed) ----------------
__device__ float g_Spart[NSPLIT*HID2];   // split-K partials for S_aug
__device__ float g_S   [HID2];           // S_aug = [X|y]^T [X|y]
__device__ float g_Wxa [HID2];           // [W_x | w_y]
__device__ float g_E   [HID2];           // W_k^T W_q
__device__ float g_G   [HID2];           // Gram of train residual stream
__device__ float g_T   [HID2];
__device__ float g_T2  [HID2];
__device__ float g_A   [LDEPTH*HID2];    // per-layer update operators
__device__ float g_u   [2*HID];
__device__ float g_d   [D_DIM];

// ---------------- generic tiled GEMM: C = alpha*op(A)*op(B) (+beta*C) ------
// logical A is MxK, B is KxN, C is MxN row-major (ldc).
// TA: A stored (K,M) row-major -> element (m,k) = A[k*lda+m]
// TB: B stored (N,K) row-major -> element (k,n) = B[n*ldb+k]
#define BM 64
#define BN 64
#define BKK 16

template<bool TA, bool TB>
__global__ void gemm_k(const float* __restrict__ A, const float* __restrict__ B,
                       float* __restrict__ C, int M, int N, int K,
                       int lda, int ldb, int ldc, float alpha, float beta)
{
    __shared__ float As[BKK][BM+4];
    __shared__ float Bs[BKK][BN+4];
    const int bm = blockIdx.y * BM;
    const int bn = blockIdx.x * BN;
    const int tid = threadIdx.x;
    const int tx = tid & 15;
    const int ty = tid >> 4;
    float acc[4][4] = {};

    for (int k0 = 0; k0 < K; k0 += BKK) {
        // load A tile
        if (TA) {
            #pragma unroll
            for (int i = tid; i < BM*BKK; i += 256) {
                int m = i & (BM-1), kk = i >> 6;
                int gm = bm + m, gk = k0 + kk;
                As[kk][m] = (gm < M && gk < K) ? A[(size_t)gk*lda + gm] : 0.f;
            }
        } else {
            #pragma unroll
            for (int i = tid; i < BM*BKK; i += 256) {
                int kk = i & (BKK-1), m = i >> 4;
                int gm = bm + m, gk = k0 + kk;
                As[kk][m] = (gm < M && gk < K) ? A[(size_t)gm*lda + gk] : 0.f;
            }
        }
        // load B tile
        if (!TB) {
            #pragma unroll
            for (int i = tid; i < BN*BKK; i += 256) {
                int n = i & (BN-1), kk = i >> 6;
                int gn = bn + n, gk = k0 + kk;
                Bs[kk][n] = (gn < N && gk < K) ? B[(size_t)gk*ldb + gn] : 0.f;
            }
        } else {
            #pragma unroll
            for (int i = tid; i < BN*BKK; i += 256) {
                int kk = i & (BKK-1), n = i >> 4;
                int gn = bn + n, gk = k0 + kk;
                Bs[kk][n] = (gn < N && gk < K) ? B[(size_t)gn*ldb + gk] : 0.f;
            }
        }
        __syncthreads();
        #pragma unroll
        for (int kk = 0; kk < BKK; kk++) {
            float4 a4 = *reinterpret_cast<const float4*>(&As[kk][ty*4]);
            float4 b4 = *reinterpret_cast<const float4*>(&Bs[kk][tx*4]);
            float a[4] = {a4.x, a4.y, a4.z, a4.w};
            float b[4] = {b4.x, b4.y, b4.z, b4.w};
            #pragma unroll
            for (int i = 0; i < 4; i++)
                #pragma unroll
                for (int j = 0; j < 4; j++)
                    acc[i][j] += a[i] * b[j];
        }
        __syncthreads();
    }

    #pragma unroll
    for (int i = 0; i < 4; i++) {
        int gm = bm + ty*4 + i;
        if (gm >= M) continue;
        #pragma unroll
        for (int j = 0; j < 4; j++) {
            int gn = bn + tx*4 + j;
            if (gn < N) {
                size_t idx = (size_t)gm*ldc + gn;
                float r = alpha * acc[i][j];
                if (beta != 0.f) r += beta * C[idx];
                C[idx] = r;
            }
        }
    }
}

// ---------------- split-K syrk of augmented matrix [X | y] ----------------
// Spart[z][i][j] = sum_{p in chunk z} aug(p,i)*aug(p,j),  aug(p,c) = c<512 ? X[p,c] : y[p]
__global__ void syrk_aug(const float* __restrict__ X, const float* __restrict__ y,
                         float* __restrict__ Spart)
{
    __shared__ float As[BKK][BM+4];
    __shared__ float Bs[BKK][BN+4];
    const int bm = blockIdx.y * BM;
    const int bn = blockIdx.x * BN;
    const int p0 = blockIdx.z * CHUNK;
    const int tid = threadIdx.x;
    const int tx = tid & 15;
    const int ty = tid >> 4;
    float acc[4][4] = {};

    for (int k0 = 0; k0 < CHUNK; k0 += BKK) {
        #pragma unroll
        for (int i = tid; i < BM*BKK; i += 256) {
            int m = i & (BM-1), kk = i >> 6;
            int p = p0 + k0 + kk;
            int c = bm + m;
            float v = 0.f;
            if (c < HID) v = (c < D_DIM) ? X[(size_t)p*D_DIM + c] : y[p];
            As[kk][m] = v;
            int c2 = bn + m;
            float v2 = 0.f;
            if (c2 < HID) v2 = (c2 < D_DIM) ? X[(size_t)p*D_DIM + c2] : y[p];
            Bs[kk][m] = v2;
        }
        __syncthreads();
        #pragma unroll
        for (int kk = 0; kk < BKK; kk++) {
            float4 a4 = *reinterpret_cast<const float4*>(&As[kk][ty*4]);
            float4 b4 = *reinterpret_cast<const float4*>(&Bs[kk][tx*4]);
            float a[4] = {a4.x, a4.y, a4.z, a4.w};
            float b[4] = {b4.x, b4.y, b4.z, b4.w};
            #pragma unroll
            for (int i = 0; i < 4; i++)
                #pragma unroll
                for (int j = 0; j < 4; j++)
                    acc[i][j] += a[i] * b[j];
        }
        __syncthreads();
    }

    float* Cp = Spart + (size_t)blockIdx.z * HID2;
    #pragma unroll
    for (int i = 0; i < 4; i++) {
        int gm = bm + ty*4 + i;
        if (gm >= HID) continue;
        #pragma unroll
        for (int j = 0; j < 4; j++) {
            int gn = bn + tx*4 + j;
            if (gn < HID) Cp[(size_t)gm*HID + gn] = acc[i][j];
        }
    }
}

__global__ void reduce_spart(const float* __restrict__ Spart, float* __restrict__ S)
{
    int i = blockIdx.x*256 + threadIdx.x;
    if (i >= HID2) return;
    float s = 0.f;
    #pragma unroll
    for (int p = 0; p < NSPLIT; p++) s += Spart[(size_t)p*HID2 + i];
    S[i] = s;
}

__global__ void build_wxa(const float* __restrict__ Wx, const float* __restrict__ wy,
                          float* __restrict__ Wxa)
{
    int i = blockIdx.x*256 + threadIdx.x;
    if (i >= HID2) return;
    int r = i / HID, c = i % HID;
    Wxa[i] = (c < D_DIM) ? Wx[(size_t)r*D_DIM + c] : wy[r];
}

__global__ void sub_k(const float* __restrict__ a, const float* __restrict__ b,
                      float* __restrict__ c, int n)
{
    int i = blockIdx.x*256 + threadIdx.x;
    if (i < n) c[i] = a[i] - b[i];
}

__global__ void copy_vec(const float* __restrict__ src, float* __restrict__ dst, int n)
{
    int i = blockIdx.x*256 + threadIdx.x;
    if (i < n) dst[i] = src[i];
}

// uout[j] = uin[j] + sum_i A[i,j] * uin[i]
__global__ void gemv_t_add(const float* __restrict__ A, const float* __restrict__ uin,
                           float* __restrict__ uout, int n)
{
    int j = blockIdx.x*256 + threadIdx.x;
    if (j >= n) return;
    float s = uin[j];
    for (int i = 0; i < n; i++) s += A[(size_t)i*n + j] * uin[i];
    uout[j] = s;
}

// d[j] = sum_i Wx[i,j] * u[i]   (i < HID, j < D)
__global__ void gemv_wx_t(const float* __restrict__ Wx, const float* __restrict__ u,
                          float* __restrict__ d)
{
    int j = blockIdx.x*256 + threadIdx.x;
    if (j >= D_DIM) return;
    float s = 0.f;
    for (int i = 0; i < HID; i++) s += Wx[(size_t)i*D_DIM + j] * u[i];
    d[j] = s;
}

// out[k] = dot(X_star[k,:], d)  — one warp per k
__global__ void out_k(const float* __restrict__ Xs, const float* __restrict__ d,
                      float* __restrict__ out)
{
    int k = blockIdx.x*8 + (threadIdx.x >> 5);
    int lane = threadIdx.x & 31;
    if (k >= KTEST) return;
    const float* row = Xs + (size_t)k * D_DIM;
    float s = 0.f;
    #pragma unroll 4
    for (int c = lane; c < D_DIM; c += 32) s += row[c] * d[c];
    #pragma unroll
    for (int o = 16; o > 0; o >>= 1) s += __shfl_xor_sync(0xFFFFFFFFu, s, o);
    if (lane == 0) out[k] = s;
}

// ---------------- host orchestration ----------------
static float* sym_addr(const void* sym) {
    void* p = nullptr;
    cudaGetSymbolAddress(&p, sym);
    return (float*)p;
}

extern "C" void kernel_launch(void* const* d_in, const int* in_sizes, int n_in,
                              void* d_out, int out_size)
{
    const float* X  = (const float*)d_in[0];   // (P, D)
    const float* y  = (const float*)d_in[1];   // (P,)
    const float* Xs = (const float*)d_in[2];   // (KTEST, D)
    const float* Wx = (const float*)d_in[3];   // (HID, D)
    const float* wy = (const float*)d_in[4];   // (HID,)
    const float* wo = (const float*)d_in[5];   // (HID,)
    const float* Wk = (const float*)d_in[6];   // (HID, HID)
    const float* Wq = (const float*)d_in[7];   // (HID, HID)
    const float* Wv = (const float*)d_in[8];   // (HID, HID)
    float* out = (float*)d_out;                // (KTEST,)

    float* Spart = sym_addr(g_Spart);
    float* S     = sym_addr(g_S);
    float* Wxa   = sym_addr(g_Wxa);
    float* E     = sym_addr(g_E);
    float* G     = sym_addr(g_G);
    float* T     = sym_addr(g_T);
    float* T2    = sym_addr(g_T2);
    float* A     = sym_addr(g_A);
    float* u     = sym_addr(g_u);
    float* dv    = sym_addr(g_d);

    const int NT = (HID + BM - 1) / BM;  // 9
    dim3 g9(NT, NT);
    const int eb = (HID2 + 255) / 256;
    const float scale = 1.0f / (LDEPTH * (float)P_CTX);

    // 1) S_aug = [X|y]^T [X|y]  (split-K, deterministic reduce)
    syrk_aug<<<dim3(NT, NT, NSPLIT), 256>>>(X, y, Spart);
    reduce_spart<<<eb, 256>>>(Spart, S);

    // 2) G_0 = Wxa * S_aug * Wxa^T ;  E = Wk^T Wq
    build_wxa<<<eb, 256>>>(Wx, wy, Wxa);
    gemm_k<false,false><<<g9, 256>>>(Wxa, S, T, HID, HID, HID, HID, HID, HID, 1.f, 0.f);
    gemm_k<false,true ><<<g9, 256>>>(T, Wxa, G, HID, HID, HID, HID, HID, HID, 1.f, 0.f);
    gemm_k<true ,false><<<g9, 256>>>(Wk, Wq, E, HID, HID, HID, HID, HID, HID, 1.f, 0.f);

    // 3) layer loop: A_l = scale*Wv*G*E ;  G = (I-A_l) G (I-A_l)^T
    for (int l = 0; l < LDEPTH; l++) {
        float* Al = A + (size_t)l * HID2;
        gemm_k<false,false><<<g9, 256>>>(G,  E, T,  HID, HID, HID, HID, HID, HID, 1.f,   0.f);
        gemm_k<false,false><<<g9, 256>>>(Wv, T, Al, HID, HID, HID, HID, HID, HID, scale, 0.f);
        gemm_k<false,false><<<g9, 256>>>(Al, G, T,  HID, HID, HID, HID, HID, HID, 1.f,   0.f);
        sub_k<<<eb, 256>>>(G, T, T2, HID2);                       // T2 = (I-A)G
        gemm_k<false,true ><<<g9, 256>>>(T2, Al, T, HID, HID, HID, HID, HID, HID, 1.f, 0.f);
        sub_k<<<eb, 256>>>(T2, T, G, HID2);                       // G = T2 (I-A)^T
    }

    // 4) backward vector: u = (I+A_1)^T ... (I+A_L)^T w_o
    copy_vec<<<3, 256>>>(wo, u, HID);
    for (int i = 0; i < LDEPTH; i++) {
        int l = LDEPTH - 1 - i;
        int cur = i & 1;
        gemv_t_add<<<3, 256>>>(A + (size_t)l * HID2, u + cur*HID, u + (cur^1)*HID, HID);
    }
    // result lands in u[0..HID) (even number of ping-pongs)

    // 5) d = Wx^T u ;  out[k] = X_star[k,:] . d
    gemv_wx_t<<<2, 256>>>(Wx, u, dv);
    out_k<<<KTEST/8, 256>>>(Xs, dv, out);
}

// round 2
// speedup vs baseline: 3.0728x; 3.0728x over previous
#include <cuda_runtime.h>

// ---------------- problem constants ----------------
#define D_DIM  512
#define HID    513
#define HIDP   576           // padded: 9 * 64
#define P_CTX  8192
#define KTEST  2048
#define LDEPTH 8
#define HIDP2  (HIDP*HIDP)
#define NZ     16            // split-K chunks for syrk
#define ZCHUNK (P_CTX/NZ)    // 512
#define NTILE  9             // 576/64
#define NPAIR  45            // upper-triangular tile pairs

// ---------------- scratch (no allocations allowed) ----------------
__device__ float g_Spart[NZ*NPAIR*64*64]; // split-K symmetric partials
__device__ float g_S   [HIDP2];           // S_aug = [X|y]^T [X|y]  (padded)
__device__ float g_Wxa [HIDP2];           // [W_x | w_y] padded
__device__ float g_WkT [HIDP2];           // Wk^T padded
__device__ float g_WqP [HIDP2];
__device__ float g_WvP [HIDP2];
__device__ float g_E   [HIDP2];           // Wk^T Wq
__device__ float g_G   [HIDP2];
__device__ float g_T   [HIDP2];
__device__ float g_T2  [HIDP2];
__device__ float g_A   [LDEPTH*HIDP2];    // per-layer update operators
__device__ float g_u   [2*HID];
__device__ float g_d   [D_DIM];

// ================= 576x576x576 GEMM, double-buffered ======================
// C = alpha * A * op(B)            (EPI==0)
// C = D - A * op(B)                (EPI==1)
// All matrices 576x576 row-major, fully padded (no bounds checks).
// TB: B used transposed (acc += A[m,k]*B[n,k]).
template<bool TB, int EPI>
__global__ __launch_bounds__(256) void gemm576(const float* __restrict__ A,
                                               const float* __restrict__ B,
                                               const float* __restrict__ Dm,
                                               float* __restrict__ C,
                                               float alpha)
{
    __shared__ float As[2][16][64+4];
    __shared__ float Bs[2][16][64+4];
    const int bm = blockIdx.y * 64;
    const int bn = blockIdx.x * 64;
    const int t  = threadIdx.x;

    // A tile load mapping: 64 rows x 16 k, float4 along k
    const int am = t >> 2;            // 0..63
    const int ak = (t & 3) * 4;       // 0,4,8,12
    // B plain: 16 k x 64 n, float4 along n
    const int bk = t >> 4;            // 0..15
    const int bnn = (t & 15) * 4;     // 0..60
    // B transposed source: 64 n x 16 k, float4 along k
    const int tbn = t >> 2;           // 0..63
    const int tbk = (t & 3) * 4;

    const int tx = (t & 15) * 4;
    const int ty = (t >> 4) * 4;

    float4 a4, b4;

    // ---- prologue: tile 0 ----
    a4 = *reinterpret_cast<const float4*>(A + (size_t)(bm + am) * HIDP + ak);
    if (!TB) b4 = *reinterpret_cast<const float4*>(B + (size_t)bk * HIDP + bn + bnn);
    else     b4 = *reinterpret_cast<const float4*>(B + (size_t)(bn + tbn) * HIDP + tbk);

    As[0][ak+0][am] = a4.x; As[0][ak+1][am] = a4.y;
    As[0][ak+2][am] = a4.z; As[0][ak+3][am] = a4.w;
    if (!TB) {
        *reinterpret_cast<float4*>(&Bs[0][bk][bnn]) = b4;
    } else {
        Bs[0][tbk+0][tbn] = b4.x; Bs[0][tbk+1][tbn] = b4.y;
        Bs[0][tbk+2][tbn] = b4.z; Bs[0][tbk+3][tbn] = b4.w;
    }
    __syncthreads();

    float acc[4][4] = {};

    #pragma unroll 1
    for (int kt = 0; kt < 36; kt++) {
        const int buf = kt & 1;
        const bool has_next = (kt < 35);
        float4 a4n, b4n;
        if (has_next) {
            const int k0 = (kt + 1) * 16;
            a4n = *reinterpret_cast<const float4*>(A + (size_t)(bm + am) * HIDP + k0 + ak);
            if (!TB) b4n = *reinterpret_cast<const float4*>(B + (size_t)(k0 + bk) * HIDP + bn + bnn);
            else     b4n = *reinterpret_cast<const float4*>(B + (size_t)(bn + tbn) * HIDP + k0 + tbk);
        }

        #pragma unroll
        for (int kk = 0; kk < 16; kk++) {
            float4 av = *reinterpret_cast<const float4*>(&As[buf][kk][ty]);
            float4 bv = *reinterpret_cast<const float4*>(&Bs[buf][kk][tx]);
            float a[4] = {av.x, av.y, av.z, av.w};
            float b[4] = {bv.x, bv.y, bv.z, bv.w};
            #pragma unroll
            for (int i = 0; i < 4; i++)
                #pragma unroll
                for (int j = 0; j < 4; j++)
                    acc[i][j] += a[i] * b[j];
        }

        if (has_next) {
            __syncthreads();
            const int nb = buf ^ 1;
            As[nb][ak+0][am] = a4n.x; As[nb][ak+1][am] = a4n.y;
            As[nb][ak+2][am] = a4n.z; As[nb][ak+3][am] = a4n.w;
            if (!TB) {
                *reinterpret_cast<float4*>(&Bs[nb][bk][bnn]) = b4n;
            } else {
                Bs[nb][tbk+0][tbn] = b4n.x; Bs[nb][tbk+1][tbn] = b4n.y;
                Bs[nb][tbk+2][tbn] = b4n.z; Bs[nb][tbk+3][tbn] = b4n.w;
            }
            __syncthreads();
        }
    }

    #pragma unroll
    for (int i = 0; i < 4; i++) {
        const size_t row = (size_t)(bm + ty + i) * HIDP + bn + tx;
        #pragma unroll
        for (int j = 0; j < 4; j++) {
            float r;
            if (EPI == 0) r = alpha * acc[i][j];
            else          r = Dm[row + j] - acc[i][j];
            C[row + j] = r;
        }
    }
}

// ============== symmetric split-K syrk of [X | y] (padded) ================
// Spart[z][pair][mi][nj] = sum_{p in chunk z} aug(p, bm+mi)*aug(p, bn+nj)
// pair enumerates (i<=j) tile pairs; aug(p,c)= c<512?X[p,c] : (c==512? y[p]:0)
__global__ __launch_bounds__(256) void syrk_aug(const float* __restrict__ X,
                                                const float* __restrict__ y,
                                                float* __restrict__ Spart)
{
    __shared__ float As[2][16][64+4];
    __shared__ float Bs[2][16][64+4];

    // decode pair index -> (ti, tj), ti<=tj
    int q = blockIdx.x;
    int ti = 0, rem = q;
    while (rem >= NTILE - ti) { rem -= NTILE - ti; ti++; }
    const int tj = ti + rem;
    const int bm = ti * 64;
    const int bn = tj * 64;
    const int p0 = blockIdx.y * ZCHUNK;

    const int t  = threadIdx.x;
    const int pk = t >> 4;            // 0..15  (row within k-tile)
    const int c4 = (t & 15) * 4;      // 0..60  (col within 64-tile)
    const int tx = (t & 15) * 4;
    const int ty = (t >> 4) * 4;

    auto load_aug = [&](int base_col, int p) -> float4 {
        if (base_col < 512) {
            return *reinterpret_cast<const float4*>(X + (size_t)p * D_DIM + base_col + c4);
        } else {
            float4 v = {0.f, 0.f, 0.f, 0.f};
            if (c4 == 0) v.x = y[p];   // column 512
            return v;
        }
    };

    float4 a4 = load_aug(bm, p0 + pk);
    float4 b4 = load_aug(bn, p0 + pk);
    As[0][pk][c4+0] = a4.x; As[0][pk][c4+1] = a4.y; As[0][pk][c4+2] = a4.z; As[0][pk][c4+3] = a4.w;
    Bs[0][pk][c4+0] = b4.x; Bs[0][pk][c4+1] = b4.y; Bs[0][pk][c4+2] = b4.z; Bs[0][pk][c4+3] = b4.w;
    __syncthreads();

    float acc[4][4] = {};
    const int NITER = ZCHUNK / 16;    // 32

    #pragma unroll 1
    for (int kt = 0; kt < NITER; kt++) {
        const int buf = kt & 1;
        const bool has_next = (kt < NITER - 1);
        float4 a4n, b4n;
        if (has_next) {
            const int p = p0 + (kt + 1) * 16 + pk;
            a4n = load_aug(bm, p);
            b4n = load_aug(bn, p);
        }
        #pragma unroll
        for (int kk = 0; kk < 16; kk++) {
            float4 av = *reinterpret_cast<const float4*>(&As[buf][kk][ty]);
            float4 bv = *reinterpret_cast<const float4*>(&Bs[buf][kk][tx]);
            float a[4] = {av.x, av.y, av.z, av.w};
            float b[4] = {bv.x, bv.y, bv.z, bv.w};
            #pragma unroll
            for (int i = 0; i < 4; i++)
                #pragma unroll
                for (int j = 0; j < 4; j++)
                    acc[i][j] += a[i] * b[j];
        }
        if (has_next) {
            __syncthreads();
            const int nb = buf ^ 1;
            As[nb][pk][c4+0] = a4n.x; As[nb][pk][c4+1] = a4n.y; As[nb][pk][c4+2] = a4n.z; As[nb][pk][c4+3] = a4n.w;
            Bs[nb][pk][c4+0] = b4n.x; Bs[nb][pk][c4+1] = b4n.y; Bs[nb][pk][c4+2] = b4n.z; Bs[nb][pk][c4+3] = b4n.w;
            __syncthreads();
        }
    }

    float* Cp = Spart + ((size_t)blockIdx.y * NPAIR + q) * 4096;
    #pragma unroll
    for (int i = 0; i < 4; i++)
        #pragma unroll
        for (int j = 0; j < 4; j++)
            Cp[(ty + i) * 64 + tx + j] = acc[i][j];
}

// reduce split-K partials, scatter symmetrically into padded S
__global__ void reduce_sym(const float* __restrict__ Spart, float* __restrict__ S)
{
    int q = blockIdx.x;               // pair
    int e = blockIdx.y * 256 + threadIdx.x;  // 0..4095
    int ti = 0, rem = q;
    while (rem >= NTILE - ti) { rem -= NTILE - ti; ti++; }
    const int tj = ti + rem;
    const int mi = e >> 6, nj = e & 63;
    float s = 0.f;
    #pragma unroll
    for (int z = 0; z < NZ; z++)
        s += Spart[((size_t)z * NPAIR + q) * 4096 + e];
    const int gm = ti * 64 + mi, gn = tj * 64 + nj;
    S[(size_t)gm * HIDP + gn] = s;
    S[(size_t)gn * HIDP + gm] = s;
}

// ---------------- padded builders ----------------
__global__ void build_wxa(const float* __restrict__ Wx, const float* __restrict__ wy,
                          float* __restrict__ dst)
{
    int idx = blockIdx.x * 256 + threadIdx.x;
    if (idx >= HIDP2) return;
    int r = idx / HIDP, c = idx % HIDP;
    float v = 0.f;
    if (r < HID) {
        if (c < D_DIM) v = Wx[(size_t)r * D_DIM + c];
        else if (c == D_DIM) v = wy[r];
    }
    dst[idx] = v;
}

__global__ void pad_copy(const float* __restrict__ src, float* __restrict__ dst)
{
    int idx = blockIdx.x * 256 + threadIdx.x;
    if (idx >= HIDP2) return;
    int r = idx / HIDP, c = idx % HIDP;
    dst[idx] = (r < HID && c < HID) ? src[(size_t)r * HID + c] : 0.f;
}

__global__ void pad_copy_T(const float* __restrict__ src, float* __restrict__ dst)
{
    int idx = blockIdx.x * 256 + threadIdx.x;
    if (idx >= HIDP2) return;
    int r = idx / HIDP, c = idx % HIDP;
    dst[idx] = (r < HID && c < HID) ? src[(size_t)c * HID + r] : 0.f;
}

// ---------------- vector tail ----------------
__global__ void copy_vec(const float* __restrict__ src, float* __restrict__ dst, int n)
{
    int i = blockIdx.x * 256 + threadIdx.x;
    if (i < n) dst[i] = src[i];
}

// uout[j] = uin[j] + sum_i A[i,j]*uin[i]   (A padded stride HIDP, real 513)
__global__ void gemv_t_add(const float* __restrict__ A, const float* __restrict__ uin,
                           float* __restrict__ uout)
{
    int j = blockIdx.x * 256 + threadIdx.x;
    if (j >= HID) return;
    float s = uin[j];
    for (int i = 0; i < HID; i++) s += A[(size_t)i * HIDP + j] * uin[i];
    uout[j] = s;
}

// d[j] = sum_i Wx[i,j]*u[i]
__global__ void gemv_wx_t(const float* __restrict__ Wx, const float* __restrict__ u,
                          float* __restrict__ d)
{
    int j = blockIdx.x * 256 + threadIdx.x;
    if (j >= D_DIM) return;
    float s = 0.f;
    for (int i = 0; i < HID; i++) s += Wx[(size_t)i * D_DIM + j] * u[i];
    d[j] = s;
}

// out[k] = dot(X_star[k,:], d)
__global__ void out_k(const float* __restrict__ Xs, const float* __restrict__ d,
                      float* __restrict__ out)
{
    int k = blockIdx.x * 8 + (threadIdx.x >> 5);
    int lane = threadIdx.x & 31;
    if (k >= KTEST) return;
    const float* row = Xs + (size_t)k * D_DIM;
    float s = 0.f;
    #pragma unroll 4
    for (int c = lane; c < D_DIM; c += 32) s += row[c] * d[c];
    #pragma unroll
    for (int o = 16; o > 0; o >>= 1) s += __shfl_xor_sync(0xFFFFFFFFu, s, o);
    if (lane == 0) out[k] = s;
}

// ---------------- host orchestration ----------------
static float* sym_addr(const void* sym) {
    void* p = nullptr;
    cudaGetSymbolAddress(&p, sym);
    return (float*)p;
}

extern "C" void kernel_launch(void* const* d_in, const int* in_sizes, int n_in,
                              void* d_out, int out_size)
{
    const float* X  = (const float*)d_in[0];
    const float* y  = (const float*)d_in[1];
    const float* Xs = (const float*)d_in[2];
    const float* Wx = (const float*)d_in[3];
    const float* wy = (const float*)d_in[4];
    const float* wo = (const float*)d_in[5];
    const float* Wk = (const float*)d_in[6];
    const float* Wq = (const float*)d_in[7];
    const float* Wv = (const float*)d_in[8];
    float* out = (float*)d_out;

    float* Spart = sym_addr(g_Spart);
    float* S     = sym_addr(g_S);
    float* Wxa   = sym_addr(g_Wxa);
    float* WkT   = sym_addr(g_WkT);
    float* WqP   = sym_addr(g_WqP);
    float* WvP   = sym_addr(g_WvP);
    float* E     = sym_addr(g_E);
    float* G     = sym_addr(g_G);
    float* T     = sym_addr(g_T);
    float* T2    = sym_addr(g_T2);
    float* A     = sym_addr(g_A);
    float* u     = sym_addr(g_u);
    float* dv    = sym_addr(g_d);

    const dim3 g9(NTILE, NTILE);
    const int eb = (HIDP2 + 255) / 256;
    const float scale = 1.0f / (LDEPTH * (float)P_CTX);

    // 1) S_aug (symmetric, split-K, deterministic)
    syrk_aug<<<dim3(NPAIR, NZ), 256>>>(X, y, Spart);
    reduce_sym<<<dim3(NPAIR, 16), 256>>>(Spart, S);

    // 2) padded operand builds
    build_wxa<<<eb, 256>>>(Wx, wy, Wxa);
    pad_copy_T<<<eb, 256>>>(Wk, WkT);
    pad_copy  <<<eb, 256>>>(Wq, WqP);
    pad_copy  <<<eb, 256>>>(Wv, WvP);

    // 3) G0 = Wxa S Wxa^T ; E = Wk^T Wq
    gemm576<false,0><<<g9, 256>>>(Wxa, S,   nullptr, T, 1.f);
    gemm576<true ,0><<<g9, 256>>>(T,   Wxa, nullptr, G, 1.f);
    gemm576<false,0><<<g9, 256>>>(WkT, WqP, nullptr, E, 1.f);

    // 4) layer loop: A_l = s*Wv*G*E ;  G = (I-A)G(I-A)^T  (fused epilogues)
    for (int l = 0; l < LDEPTH; l++) {
        float* Al = A + (size_t)l * HIDP2;
        gemm576<false,0><<<g9, 256>>>(G,   E,  nullptr, T,  1.f);
        gemm576<false,0><<<g9, 256>>>(WvP, T,  nullptr, Al, scale);
        gemm576<false,1><<<g9, 256>>>(Al,  G,  G,       T2, 1.f);   // T2 = G - Al*G
        gemm576<true ,1><<<g9, 256>>>(T2,  Al, T2,      G,  1.f);   // G  = T2 - T2*Al^T
    }

    // 5) u = prod (I+A_l)^T w_o  (l from L-1 down to 0)
    copy_vec<<<3, 256>>>(wo, u, HID);
    for (int i = 0; i < LDEPTH; i++) {
        int l = LDEPTH - 1 - i;
        int cur = i & 1;
        gemv_t_add<<<3, 256>>>(A + (size_t)l * HIDP2, u + cur * HID, u + (cur ^ 1) * HID);
    }

    // 6) d = Wx^T u ;  out = X_star d
    gemv_wx_t<<<2, 256>>>(Wx, u, dv);
    out_k<<<KTEST / 8, 256>>>(Xs, dv, out);
}